// round 2
// baseline (speedup 1.0000x reference)
#include <cuda_runtime.h>
#include <cstdint>
#include <cstddef>

// Problem dims
#define U1 513          // U+1 timesteps
#define NB 64           // batch
#define ND 1024         // hidden / predictor dim
#define TD 3072         // 3*D gate dim
#define NJ 1024         // joiner dim

// Scratch (static __device__ arrays; no allocation allowed)
__device__ float g_gx[(size_t)U1 * NB * TD];   // [u][b][3D] input-side gate preacts
__device__ float g_hs[(size_t)U1 * NB * ND];   // [u][b][D]  hidden states
__device__ float g_h0[NB * ND];                // broadcast initial state

__device__ __forceinline__ uint32_t f2tf32(float x) {
    uint32_t r;
    asm("cvt.rna.tf32.f32 %0, %1;" : "=r"(r) : "f"(x));
    return r;
}

__device__ __forceinline__ void mma8(float c[4], const uint32_t a[4], const uint32_t b[2]) {
    asm volatile(
        "mma.sync.aligned.m16n8k8.row.col.f32.tf32.tf32.f32 "
        "{%0,%1,%2,%3},{%4,%5,%6,%7},{%8,%9},{%0,%1,%2,%3};\n"
        : "+f"(c[0]), "+f"(c[1]), "+f"(c[2]), "+f"(c[3])
        : "r"(a[0]), "r"(a[1]), "r"(a[2]), "r"(a[3]), "r"(b[0]), "r"(b[1]));
}

// ---------------------------------------------------------------------------
// h0 broadcast: g_h0[b][d] = initial_state[d]
// ---------------------------------------------------------------------------
__global__ void k_h0(const float* __restrict__ init) {
    int i = blockIdx.x * blockDim.x + threadIdx.x;   // 0 .. 65535
    g_h0[i] = init[i & (ND - 1)];
}

// ---------------------------------------------------------------------------
// GEMM 1: g_gx[r][g] = embed[token(r)] . weight_ih[g] + bias_ih[g]
//   r = u*64 + b,  token = (u==0) ? 0 : y[b][u-1]
// Tile: 64x64, BK=32, 128 threads (4 warps, warp tile 32x32), tf32 mma.
// ---------------------------------------------------------------------------
__global__ void __launch_bounds__(128) k_gx(const int*  __restrict__ y,
                                            const float* __restrict__ embed,
                                            const float* __restrict__ wih,
                                            const float* __restrict__ bih) {
    __shared__ float As[64][36];
    __shared__ float Bs[64][36];
    __shared__ int   tok[64];

    const int tid  = threadIdx.x;
    const int lane = tid & 31;
    const int wid  = tid >> 5;
    const int wm   = (wid & 1) * 32;
    const int wn   = (wid >> 1) * 32;
    const int bm0  = blockIdx.y * 64;
    const int bn0  = blockIdx.x * 64;

    if (tid < 64) {
        int r = bm0 + tid;
        int u = r >> 6, b = r & 63;
        tok[tid] = (u == 0) ? 0 : y[b * 512 + u - 1];
    }
    __syncthreads();

    float c[2][4][4];
#pragma unroll
    for (int mt = 0; mt < 2; mt++)
#pragma unroll
        for (int nt = 0; nt < 4; nt++)
#pragma unroll
            for (int r = 0; r < 4; r++) c[mt][nt][r] = 0.f;

    for (int k0 = 0; k0 < ND; k0 += 32) {
#pragma unroll
        for (int i = 0; i < 4; i++) {               // stage A (gathered rows)
            int q   = tid + 128 * i;                // 0..511 -> 64x8 float4
            int row = q >> 3;
            int kk  = (q & 7) * 4;
            float4 v = *(const float4*)(embed + (size_t)tok[row] * ND + k0 + kk);
            uint4 t;
            t.x = f2tf32(v.x); t.y = f2tf32(v.y); t.z = f2tf32(v.z); t.w = f2tf32(v.w);
            *(uint4*)&As[row][kk] = t;
        }
#pragma unroll
        for (int i = 0; i < 4; i++) {               // stage B (weight rows)
            int q   = tid + 128 * i;
            int row = q >> 3;
            int kk  = (q & 7) * 4;
            float4 v = *(const float4*)(wih + (size_t)(bn0 + row) * ND + k0 + kk);
            uint4 t;
            t.x = f2tf32(v.x); t.y = f2tf32(v.y); t.z = f2tf32(v.z); t.w = f2tf32(v.w);
            *(uint4*)&Bs[row][kk] = t;
        }
        __syncthreads();

#pragma unroll
        for (int k8 = 0; k8 < 4; k8++) {
            const int ac = k8 * 8 + (lane & 3);
            uint32_t a[2][4];
#pragma unroll
            for (int mt = 0; mt < 2; mt++) {
                int ar = wm + mt * 16 + (lane >> 2);
                a[mt][0] = __float_as_uint(As[ar][ac]);
                a[mt][1] = __float_as_uint(As[ar + 8][ac]);
                a[mt][2] = __float_as_uint(As[ar][ac + 4]);
                a[mt][3] = __float_as_uint(As[ar + 8][ac + 4]);
            }
#pragma unroll
            for (int nt = 0; nt < 4; nt++) {
                int br = wn + nt * 8 + (lane >> 2);
                uint32_t b[2];
                b[0] = __float_as_uint(Bs[br][ac]);
                b[1] = __float_as_uint(Bs[br][ac + 4]);
#pragma unroll
                for (int mt = 0; mt < 2; mt++) mma8(c[mt][nt], a[mt], b);
            }
        }
        __syncthreads();
    }

#pragma unroll
    for (int mt = 0; mt < 2; mt++)
#pragma unroll
        for (int nt = 0; nt < 4; nt++)
#pragma unroll
            for (int r = 0; r < 4; r++) {
                int row = bm0 + wm + mt * 16 + (lane >> 2) + ((r >> 1) * 8);
                int col = bn0 + wn + nt * 8 + (lane & 3) * 2 + (r & 1);
                g_gx[(size_t)row * TD + col] = c[mt][nt][r] + bih[col];
            }
}

// ---------------------------------------------------------------------------
// GRU step t (one kernel launch per step; launch boundary = grid sync).
// 64 CTAs; CTA c owns j in [16c, 16c+16). It computes gh for weight rows
// {j, D+j, 2D+j} (48 local cols), then the gate update for its j-slice only
// -> no cross-CTA dependency within a step.
// ---------------------------------------------------------------------------
__global__ void __launch_bounds__(128) k_gru(const float* __restrict__ whh,
                                             const float* __restrict__ bhh,
                                             int t) {
    __shared__ float Hs[64][36];
    __shared__ float Ws[48][36];

    const float* __restrict__ hprev =
        (t == 0) ? g_h0 : (g_hs + (size_t)(t - 1) * NB * ND);

    const int tid  = threadIdx.x;
    const int lane = tid & 31;
    const int w    = tid >> 5;                 // warp -> M tile (16 rows of batch)
    const int c0   = blockIdx.x * 16;          // j base

    float acc[6][4];
#pragma unroll
    for (int nt = 0; nt < 6; nt++)
#pragma unroll
        for (int r = 0; r < 4; r++) acc[nt][r] = 0.f;

    for (int k0 = 0; k0 < ND; k0 += 32) {
#pragma unroll
        for (int i = 0; i < 4; i++) {               // stage h chunk 64x32
            int q   = tid + 128 * i;
            int row = q >> 3;
            int kk  = (q & 7) * 4;
            float4 v = *(const float4*)(hprev + (size_t)row * ND + k0 + kk);
            uint4 u;
            u.x = f2tf32(v.x); u.y = f2tf32(v.y); u.z = f2tf32(v.z); u.w = f2tf32(v.w);
            *(uint4*)&Hs[row][kk] = u;
        }
#pragma unroll
        for (int i = 0; i < 3; i++) {               // stage W chunk 48x32
            int q   = tid + 128 * i;
            int n   = q >> 3;                       // 0..47 local row
            int kk  = (q & 7) * 4;
            int grow = (n >> 4) * ND + c0 + (n & 15);
            float4 v = *(const float4*)(whh + (size_t)grow * ND + k0 + kk);
            uint4 u;
            u.x = f2tf32(v.x); u.y = f2tf32(v.y); u.z = f2tf32(v.z); u.w = f2tf32(v.w);
            *(uint4*)&Ws[n][kk] = u;
        }
        __syncthreads();

#pragma unroll
        for (int k8 = 0; k8 < 4; k8++) {
            const int ac = k8 * 8 + (lane & 3);
            const int ar = w * 16 + (lane >> 2);
            uint32_t a[4];
            a[0] = __float_as_uint(Hs[ar][ac]);
            a[1] = __float_as_uint(Hs[ar + 8][ac]);
            a[2] = __float_as_uint(Hs[ar][ac + 4]);
            a[3] = __float_as_uint(Hs[ar + 8][ac + 4]);
#pragma unroll
            for (int nt = 0; nt < 6; nt++) {
                int br = nt * 8 + (lane >> 2);
                uint32_t b[2];
                b[0] = __float_as_uint(Ws[br][ac]);
                b[1] = __float_as_uint(Ws[br][ac + 4]);
                mma8(acc[nt], a, b);
            }
        }
        __syncthreads();
    }

    // Gate update. acc layout: local col n = gate*16 + jj; nt q/q+2/q+4 give
    // (r,z,n) gates at the same (b, jj) fragment position.
    const float* __restrict__ gx = g_gx + (size_t)t * NB * TD;
    float* __restrict__ hout = g_hs + (size_t)t * NB * ND;

#pragma unroll
    for (int q = 0; q < 2; q++) {
#pragma unroll
        for (int r = 0; r < 4; r++) {
            int b  = w * 16 + (lane >> 2) + (r >> 1) * 8;
            int jj = 8 * q + (lane & 3) * 2 + (r & 1);
            int j  = c0 + jj;
            float ghr = acc[q][r]     + bhh[j];
            float ghz = acc[q + 2][r] + bhh[ND + j];
            float ghn = acc[q + 4][r] + bhh[2 * ND + j];
            float gxr = gx[(size_t)b * TD + j];
            float gxz = gx[(size_t)b * TD + ND + j];
            float gxn = gx[(size_t)b * TD + 2 * ND + j];
            float hp  = hprev[(size_t)b * ND + j];
            float rg = 1.f / (1.f + expf(-(gxr + ghr)));
            float zg = 1.f / (1.f + expf(-(gxz + ghz)));
            float ng = tanhf(gxn + rg * ghn);
            hout[(size_t)b * ND + j] = (1.f - zg) * ng + zg * hp;
        }
    }
}

// ---------------------------------------------------------------------------
// GEMM 3: out[b][u][j] = hs[u][b] . linear_w[j] + linear_b[j]
// Same tiling as k_gx; A rows come from g_hs, epilogue remaps (u,b)->(b,u).
// ---------------------------------------------------------------------------
__global__ void __launch_bounds__(128) k_out(const float* __restrict__ lw,
                                             const float* __restrict__ lb,
                                             float* __restrict__ out) {
    __shared__ float As[64][36];
    __shared__ float Bs[64][36];

    const int tid  = threadIdx.x;
    const int lane = tid & 31;
    const int wid  = tid >> 5;
    const int wm   = (wid & 1) * 32;
    const int wn   = (wid >> 1) * 32;
    const int bm0  = blockIdx.y * 64;
    const int bn0  = blockIdx.x * 64;

    float c[2][4][4];
#pragma unroll
    for (int mt = 0; mt < 2; mt++)
#pragma unroll
        for (int nt = 0; nt < 4; nt++)
#pragma unroll
            for (int r = 0; r < 4; r++) c[mt][nt][r] = 0.f;

    for (int k0 = 0; k0 < ND; k0 += 32) {
#pragma unroll
        for (int i = 0; i < 4; i++) {
            int q   = tid + 128 * i;
            int row = q >> 3;
            int kk  = (q & 7) * 4;
            float4 v = *(const float4*)(g_hs + (size_t)(bm0 + row) * ND + k0 + kk);
            uint4 t;
            t.x = f2tf32(v.x); t.y = f2tf32(v.y); t.z = f2tf32(v.z); t.w = f2tf32(v.w);
            *(uint4*)&As[row][kk] = t;
        }
#pragma unroll
        for (int i = 0; i < 4; i++) {
            int q   = tid + 128 * i;
            int row = q >> 3;
            int kk  = (q & 7) * 4;
            float4 v = *(const float4*)(lw + (size_t)(bn0 + row) * ND + k0 + kk);
            uint4 t;
            t.x = f2tf32(v.x); t.y = f2tf32(v.y); t.z = f2tf32(v.z); t.w = f2tf32(v.w);
            *(uint4*)&Bs[row][kk] = t;
        }
        __syncthreads();

#pragma unroll
        for (int k8 = 0; k8 < 4; k8++) {
            const int ac = k8 * 8 + (lane & 3);
            uint32_t a[2][4];
#pragma unroll
            for (int mt = 0; mt < 2; mt++) {
                int ar = wm + mt * 16 + (lane >> 2);
                a[mt][0] = __float_as_uint(As[ar][ac]);
                a[mt][1] = __float_as_uint(As[ar + 8][ac]);
                a[mt][2] = __float_as_uint(As[ar][ac + 4]);
                a[mt][3] = __float_as_uint(As[ar + 8][ac + 4]);
            }
#pragma unroll
            for (int nt = 0; nt < 4; nt++) {
                int br = wn + nt * 8 + (lane >> 2);
                uint32_t b[2];
                b[0] = __float_as_uint(Bs[br][ac]);
                b[1] = __float_as_uint(Bs[br][ac + 4]);
#pragma unroll
                for (int mt = 0; mt < 2; mt++) mma8(c[mt][nt], a[mt], b);
            }
        }
        __syncthreads();
    }

#pragma unroll
    for (int mt = 0; mt < 2; mt++)
#pragma unroll
        for (int nt = 0; nt < 4; nt++)
#pragma unroll
            for (int r = 0; r < 4; r++) {
                int row = bm0 + wm + mt * 16 + (lane >> 2) + ((r >> 1) * 8);
                int col = bn0 + wn + nt * 8 + (lane & 3) * 2 + (r & 1);
                int u = row >> 6, b = row & 63;
                out[((size_t)b * U1 + u) * NJ + col] = c[mt][nt][r] + lb[col];
            }
}

// ---------------------------------------------------------------------------
// Launch. All default-stream launches -> stream order provides dependencies;
// fully graph-capturable (no sync, no alloc, no memcpy).
// Inputs (metadata order): y, embed, weight_ih, bias_ih, weight_hh, bias_hh,
//                          linear_w, linear_b, initial_state
// ---------------------------------------------------------------------------
extern "C" void kernel_launch(void* const* d_in, const int* in_sizes, int n_in,
                              void* d_out, int out_size) {
    const int*   y     = (const int*)  d_in[0];
    const float* embed = (const float*)d_in[1];
    const float* wih   = (const float*)d_in[2];
    const float* bih   = (const float*)d_in[3];
    const float* whh   = (const float*)d_in[4];
    const float* bhh   = (const float*)d_in[5];
    const float* lw    = (const float*)d_in[6];
    const float* lb    = (const float*)d_in[7];
    const float* init  = (const float*)d_in[8];

    k_h0<<<(NB * ND) / 256, 256>>>(init);
    k_gx<<<dim3(TD / 64, (U1 * NB) / 64), 128>>>(y, embed, wih, bih);
    for (int t = 0; t < U1; t++) {
        k_gru<<<ND / 16, 128>>>(whh, bhh, t);
    }
    k_out<<<dim3(NJ / 64, (U1 * NB) / 64), 128>>>(lw, lb, (float*)d_out);
}

// round 3
// speedup vs baseline: 1.7256x; 1.7256x over previous
#include <cuda_runtime.h>
#include <cstdint>
#include <cstddef>

// Problem dims
#define U1 513          // U+1 timesteps
#define NB 64           // batch
#define ND 1024         // hidden / predictor dim
#define TD 3072         // 3*D gate dim
#define NJ 1024         // joiner dim

// Scratch (static __device__ arrays; no allocation allowed)
__device__ float g_gx[(size_t)U1 * NB * TD];   // [u][b][3D] input-side gate preacts
__device__ float g_hs[(size_t)U1 * NB * ND];   // [u][b][D]  hidden states
__device__ float g_h0[NB * ND];                // broadcast initial state
__device__ int   g_bar[U1];                    // per-step grid barrier counters

__device__ __forceinline__ uint32_t f2tf32(float x) {
    uint32_t r;
    asm("cvt.rna.tf32.f32 %0, %1;" : "=r"(r) : "f"(x));
    return r;
}

__device__ __forceinline__ void mma8(float c[4], const uint32_t a[4], const uint32_t b[2]) {
    asm volatile(
        "mma.sync.aligned.m16n8k8.row.col.f32.tf32.tf32.f32 "
        "{%0,%1,%2,%3},{%4,%5,%6,%7},{%8,%9},{%0,%1,%2,%3};\n"
        : "+f"(c[0]), "+f"(c[1]), "+f"(c[2]), "+f"(c[3])
        : "r"(a[0]), "r"(a[1]), "r"(a[2]), "r"(a[3]), "r"(b[0]), "r"(b[1]));
}

// ---------------------------------------------------------------------------
// h0 broadcast + barrier reset (runs before the persistent kernel each replay)
// ---------------------------------------------------------------------------
__global__ void k_h0(const float* __restrict__ init) {
    int i = blockIdx.x * blockDim.x + threadIdx.x;   // 0 .. 65535
    g_h0[i] = init[i & (ND - 1)];
    if (i < U1) g_bar[i] = 0;
}

// ---------------------------------------------------------------------------
// GEMM 1: g_gx[r][g] = embed[token(r)] . weight_ih[g] + bias_ih[g]
// ---------------------------------------------------------------------------
__global__ void __launch_bounds__(128) k_gx(const int*  __restrict__ y,
                                            const float* __restrict__ embed,
                                            const float* __restrict__ wih,
                                            const float* __restrict__ bih) {
    __shared__ float As[64][36];
    __shared__ float Bs[64][36];
    __shared__ int   tok[64];

    const int tid  = threadIdx.x;
    const int lane = tid & 31;
    const int wid  = tid >> 5;
    const int wm   = (wid & 1) * 32;
    const int wn   = (wid >> 1) * 32;
    const int bm0  = blockIdx.y * 64;
    const int bn0  = blockIdx.x * 64;

    if (tid < 64) {
        int r = bm0 + tid;
        int u = r >> 6, b = r & 63;
        tok[tid] = (u == 0) ? 0 : y[b * 512 + u - 1];
    }
    __syncthreads();

    float c[2][4][4];
#pragma unroll
    for (int mt = 0; mt < 2; mt++)
#pragma unroll
        for (int nt = 0; nt < 4; nt++)
#pragma unroll
            for (int r = 0; r < 4; r++) c[mt][nt][r] = 0.f;

    for (int k0 = 0; k0 < ND; k0 += 32) {
#pragma unroll
        for (int i = 0; i < 4; i++) {
            int q   = tid + 128 * i;
            int row = q >> 3;
            int kk  = (q & 7) * 4;
            float4 v = *(const float4*)(embed + (size_t)tok[row] * ND + k0 + kk);
            uint4 t;
            t.x = f2tf32(v.x); t.y = f2tf32(v.y); t.z = f2tf32(v.z); t.w = f2tf32(v.w);
            *(uint4*)&As[row][kk] = t;
        }
#pragma unroll
        for (int i = 0; i < 4; i++) {
            int q   = tid + 128 * i;
            int row = q >> 3;
            int kk  = (q & 7) * 4;
            float4 v = *(const float4*)(wih + (size_t)(bn0 + row) * ND + k0 + kk);
            uint4 t;
            t.x = f2tf32(v.x); t.y = f2tf32(v.y); t.z = f2tf32(v.z); t.w = f2tf32(v.w);
            *(uint4*)&Bs[row][kk] = t;
        }
        __syncthreads();

#pragma unroll
        for (int k8 = 0; k8 < 4; k8++) {
            const int ac = k8 * 8 + (lane & 3);
            uint32_t a[2][4];
#pragma unroll
            for (int mt = 0; mt < 2; mt++) {
                int ar = wm + mt * 16 + (lane >> 2);
                a[mt][0] = __float_as_uint(As[ar][ac]);
                a[mt][1] = __float_as_uint(As[ar + 8][ac]);
                a[mt][2] = __float_as_uint(As[ar][ac + 4]);
                a[mt][3] = __float_as_uint(As[ar + 8][ac + 4]);
            }
#pragma unroll
            for (int nt = 0; nt < 4; nt++) {
                int br = wn + nt * 8 + (lane >> 2);
                uint32_t b[2];
                b[0] = __float_as_uint(Bs[br][ac]);
                b[1] = __float_as_uint(Bs[br][ac + 4]);
#pragma unroll
                for (int mt = 0; mt < 2; mt++) mma8(c[mt][nt], a[mt], b);
            }
        }
        __syncthreads();
    }

#pragma unroll
    for (int mt = 0; mt < 2; mt++)
#pragma unroll
        for (int nt = 0; nt < 4; nt++)
#pragma unroll
            for (int r = 0; r < 4; r++) {
                int row = bm0 + wm + mt * 16 + (lane >> 2) + ((r >> 1) * 8);
                int col = bn0 + wn + nt * 8 + (lane & 3) * 2 + (r & 1);
                g_gx[(size_t)row * TD + col] = c[mt][nt][r] + bih[col];
            }
}

// ---------------------------------------------------------------------------
// Persistent GRU: 64 CTAs (one per 16-col j slice), 256 threads (8 warps).
// Weights (48 rows x 1024, tf32) cached in SMEM once. Per step:
//   - h broadcast read from global (L2-resident), chunked k=32, reg-prefetch x2
//   - 8 warps = m-split(2) x k-split(4): each warp 2 m16 tiles, all 6 n8
//     tiles, one k8 per 32-chunk -> min fragment traffic
//   - 3-round smem reduction of k partials into wk==0 warps
//   - gate epilogue + h write by wk==0 warps
//   - grid barrier: per-step monotonic atomic counter + fence
// SMEM: W 48x1028 f + Hb 2x64x36 f + Red 2x48x32 f = 228096 B
// ---------------------------------------------------------------------------
#define WSTR 1028
#define HSTR 36

__global__ void __launch_bounds__(256, 1) k_gru_persist(
        const float* __restrict__ whh,
        const float* __restrict__ bhh) {
    extern __shared__ float sm[];
    float* Ws  = sm;                       // [48][1028]
    float* Hb  = sm + 48 * WSTR;           // [2][64][36]
    float* Red = Hb + 2 * 64 * HSTR;       // [2][48][32]

    const int tid  = threadIdx.x;
    const int lane = tid & 31;
    const int w    = tid >> 5;
    const int wm   = w & 1;        // m-half: rows [wm*32, wm*32+32)
    const int wk   = w >> 1;       // k-quarter: k8 index wk within each 32-chunk
    const int c0   = blockIdx.x * 16;

    // ---- stage weights (once): local row n -> whh[(n/16)*1024 + c0 + n%16]
    for (int i = tid; i < 48 * 256; i += 256) {
        int row = i >> 8;            // 0..47
        int c4  = (i & 255) * 4;     // 0..1020
        int grow = (row >> 4) * ND + c0 + (row & 15);
        float4 v = *(const float4*)(whh + (size_t)grow * ND + c4);
        uint4 t;
        t.x = f2tf32(v.x); t.y = f2tf32(v.y); t.z = f2tf32(v.z); t.w = f2tf32(v.w);
        *(uint4*)&Ws[row * WSTR + c4] = t;
    }
    __syncthreads();

    // per-thread staging indices for h chunks: float4 idx tid and tid+256
    const int sr0 = tid >> 3;            // row of first float4
    const int sc0 = (tid & 7) * 4;       // col
    const int sr1 = (tid + 256) >> 3;
    const int sc1 = ((tid + 256) & 7) * 4;

#pragma unroll 1
    for (int t = 0; t < U1; t++) {
        const float* __restrict__ hprev =
            (t == 0) ? g_h0 : (g_hs + (size_t)(t - 1) * NB * ND);

        float acc[2][6][4];
#pragma unroll
        for (int mt = 0; mt < 2; mt++)
#pragma unroll
            for (int nt = 0; nt < 6; nt++)
#pragma unroll
                for (int r = 0; r < 4; r++) acc[mt][nt][r] = 0.f;

        // prefetch chunks 0 and 1
        float4 ra0 = *(const float4*)(hprev + (size_t)sr0 * ND + sc0);
        float4 ra1 = *(const float4*)(hprev + (size_t)sr1 * ND + sc1);
        float4 rb0 = *(const float4*)(hprev + (size_t)sr0 * ND + 32 + sc0);
        float4 rb1 = *(const float4*)(hprev + (size_t)sr1 * ND + 32 + sc1);

#pragma unroll 1
        for (int c = 0; c < 32; c++) {
            // store chunk c
            float* hb = Hb + (c & 1) * 64 * HSTR;
            {
                uint4 u;
                u.x = f2tf32(ra0.x); u.y = f2tf32(ra0.y);
                u.z = f2tf32(ra0.z); u.w = f2tf32(ra0.w);
                *(uint4*)&hb[sr0 * HSTR + sc0] = u;
                u.x = f2tf32(ra1.x); u.y = f2tf32(ra1.y);
                u.z = f2tf32(ra1.z); u.w = f2tf32(ra1.w);
                *(uint4*)&hb[sr1 * HSTR + sc1] = u;
            }
            __syncthreads();

            ra0 = rb0; ra1 = rb1;
            if (c + 2 < 32) {
                const float* src = hprev + (c + 2) * 32;
                rb0 = *(const float4*)(src + (size_t)sr0 * ND + sc0);
                rb1 = *(const float4*)(src + (size_t)sr1 * ND + sc1);
            }

            // mma: this warp handles k8 = wk of this chunk
            const int ac = wk * 8 + (lane & 3);       // col in Hb
            const int kg = c * 32 + ac;               // col in Ws
            uint32_t a[2][4];
#pragma unroll
            for (int mt = 0; mt < 2; mt++) {
                int ar = wm * 32 + mt * 16 + (lane >> 2);
                a[mt][0] = __float_as_uint(hb[ar * HSTR + ac]);
                a[mt][1] = __float_as_uint(hb[(ar + 8) * HSTR + ac]);
                a[mt][2] = __float_as_uint(hb[ar * HSTR + ac + 4]);
                a[mt][3] = __float_as_uint(hb[(ar + 8) * HSTR + ac + 4]);
            }
#pragma unroll
            for (int nt = 0; nt < 6; nt++) {
                int br = nt * 8 + (lane >> 2);
                uint32_t b[2];
                b[0] = __float_as_uint(Ws[br * WSTR + kg]);
                b[1] = __float_as_uint(Ws[br * WSTR + kg + 4]);
                mma8(acc[0][nt], a[0], b);
                mma8(acc[1][nt], a[1], b);
            }
        }
        __syncthreads();

        // ---- reduce k-partials into wk==0 warps (3 rounds via 12KB buffer)
        float* af = (float*)acc;   // 48 floats
#pragma unroll 1
        for (int src = 1; src < 4; src++) {
            if (wk == src) {
                float* rb = Red + wm * 48 * 32;
#pragma unroll
                for (int i = 0; i < 48; i++) rb[i * 32 + lane] = af[i];
            }
            __syncthreads();
            if (wk == 0) {
                const float* rb = Red + wm * 48 * 32;
#pragma unroll
                for (int i = 0; i < 48; i++) af[i] += rb[i * 32 + lane];
            }
            __syncthreads();
        }

        // ---- gate epilogue (wk==0 warps only: w=0 -> rows 0..31, w=1 -> 32..63)
        if (wk == 0) {
            const float* __restrict__ gx = g_gx + (size_t)t * NB * TD;
            float* __restrict__ hout = g_hs + (size_t)t * NB * ND;
#pragma unroll
            for (int mt = 0; mt < 2; mt++) {
#pragma unroll
                for (int q = 0; q < 2; q++) {
#pragma unroll
                    for (int r = 0; r < 4; r++) {
                        int b  = wm * 32 + mt * 16 + (lane >> 2) + (r >> 1) * 8;
                        int jj = 8 * q + (lane & 3) * 2 + (r & 1);
                        int j  = c0 + jj;
                        float ghr = acc[mt][q][r]     + bhh[j];
                        float ghz = acc[mt][q + 2][r] + bhh[ND + j];
                        float ghn = acc[mt][q + 4][r] + bhh[2 * ND + j];
                        float gxr = gx[(size_t)b * TD + j];
                        float gxz = gx[(size_t)b * TD + ND + j];
                        float gxn = gx[(size_t)b * TD + 2 * ND + j];
                        float hp  = hprev[(size_t)b * ND + j];
                        float rg = 1.f / (1.f + expf(-(gxr + ghr)));
                        float zg = 1.f / (1.f + expf(-(gxz + ghz)));
                        float ng = tanhf(gxn + rg * ghn);
                        hout[(size_t)b * ND + j] = (1.f - zg) * ng + zg * hp;
                    }
                }
            }
        }

        // ---- grid barrier for step t
        __syncthreads();
        if (tid == 0) {
            __threadfence();
            atomicAdd(&g_bar[t], 1);
            while (*(volatile int*)&g_bar[t] < 64) __nanosleep(40);
            __threadfence();
        }
        __syncthreads();
    }
}

// ---------------------------------------------------------------------------
// GEMM 3: out[b][u][j] = hs[u][b] . linear_w[j] + linear_b[j]
// ---------------------------------------------------------------------------
__global__ void __launch_bounds__(128) k_out(const float* __restrict__ lw,
                                             const float* __restrict__ lb,
                                             float* __restrict__ out) {
    __shared__ float As[64][36];
    __shared__ float Bs[64][36];

    const int tid  = threadIdx.x;
    const int lane = tid & 31;
    const int wid  = tid >> 5;
    const int wm   = (wid & 1) * 32;
    const int wn   = (wid >> 1) * 32;
    const int bm0  = blockIdx.y * 64;
    const int bn0  = blockIdx.x * 64;

    float c[2][4][4];
#pragma unroll
    for (int mt = 0; mt < 2; mt++)
#pragma unroll
        for (int nt = 0; nt < 4; nt++)
#pragma unroll
            for (int r = 0; r < 4; r++) c[mt][nt][r] = 0.f;

    for (int k0 = 0; k0 < ND; k0 += 32) {
#pragma unroll
        for (int i = 0; i < 4; i++) {
            int q   = tid + 128 * i;
            int row = q >> 3;
            int kk  = (q & 7) * 4;
            float4 v = *(const float4*)(g_hs + (size_t)(bm0 + row) * ND + k0 + kk);
            uint4 t;
            t.x = f2tf32(v.x); t.y = f2tf32(v.y); t.z = f2tf32(v.z); t.w = f2tf32(v.w);
            *(uint4*)&As[row][kk] = t;
        }
#pragma unroll
        for (int i = 0; i < 4; i++) {
            int q   = tid + 128 * i;
            int row = q >> 3;
            int kk  = (q & 7) * 4;
            float4 v = *(const float4*)(lw + (size_t)(bn0 + row) * ND + k0 + kk);
            uint4 t;
            t.x = f2tf32(v.x); t.y = f2tf32(v.y); t.z = f2tf32(v.z); t.w = f2tf32(v.w);
            *(uint4*)&Bs[row][kk] = t;
        }
        __syncthreads();

#pragma unroll
        for (int k8 = 0; k8 < 4; k8++) {
            const int ac = k8 * 8 + (lane & 3);
            uint32_t a[2][4];
#pragma unroll
            for (int mt = 0; mt < 2; mt++) {
                int ar = wm + mt * 16 + (lane >> 2);
                a[mt][0] = __float_as_uint(As[ar][ac]);
                a[mt][1] = __float_as_uint(As[ar + 8][ac]);
                a[mt][2] = __float_as_uint(As[ar][ac + 4]);
                a[mt][3] = __float_as_uint(As[ar + 8][ac + 4]);
            }
#pragma unroll
            for (int nt = 0; nt < 4; nt++) {
                int br = wn + nt * 8 + (lane >> 2);
                uint32_t b[2];
                b[0] = __float_as_uint(Bs[br][ac]);
                b[1] = __float_as_uint(Bs[br][ac + 4]);
#pragma unroll
                for (int mt = 0; mt < 2; mt++) mma8(c[mt][nt], a[mt], b);
            }
        }
        __syncthreads();
    }

#pragma unroll
    for (int mt = 0; mt < 2; mt++)
#pragma unroll
        for (int nt = 0; nt < 4; nt++)
#pragma unroll
            for (int r = 0; r < 4; r++) {
                int row = bm0 + wm + mt * 16 + (lane >> 2) + ((r >> 1) * 8);
                int col = bn0 + wn + nt * 8 + (lane & 3) * 2 + (r & 1);
                int u = row >> 6, b = row & 63;
                out[((size_t)b * U1 + u) * NJ + col] = c[mt][nt][r] + lb[col];
            }
}

// ---------------------------------------------------------------------------
// Launch. Stream-ordered; graph-capturable (no sync/alloc/memcpy).
// ---------------------------------------------------------------------------
extern "C" void kernel_launch(void* const* d_in, const int* in_sizes, int n_in,
                              void* d_out, int out_size) {
    const int*   y     = (const int*)  d_in[0];
    const float* embed = (const float*)d_in[1];
    const float* wih   = (const float*)d_in[2];
    const float* bih   = (const float*)d_in[3];
    const float* whh   = (const float*)d_in[4];
    const float* bhh   = (const float*)d_in[5];
    const float* lw    = (const float*)d_in[6];
    const float* lb    = (const float*)d_in[7];
    const float* init  = (const float*)d_in[8];

    static int smem_set = 0;
    const int smem_bytes = (48 * WSTR + 2 * 64 * HSTR + 2 * 48 * 32) * 4;
    if (!smem_set) {
        cudaFuncSetAttribute(k_gru_persist,
                             cudaFuncAttributeMaxDynamicSharedMemorySize,
                             smem_bytes);
        smem_set = 1;
    }

    k_h0<<<(NB * ND) / 256, 256>>>(init);
    k_gx<<<dim3(TD / 64, (U1 * NB) / 64), 128>>>(y, embed, wih, bih);
    k_gru_persist<<<64, 256, smem_bytes>>>(whh, bhh);
    k_out<<<dim3(NJ / 64, (U1 * NB) / 64), 128>>>(lw, lb, (float*)d_out);
}